// round 5
// baseline (speedup 1.0000x reference)
#include <cuda_runtime.h>

typedef unsigned long long ull;
#define NBATCH 4
#define NVERT 512
#define NROWS (NBATCH*NVERT)
#define ABS2 0x7fffffff7fffffffULL

// scratch (allocation-free rule: device globals)
__device__ float g_v [NROWS*64];
__device__ float g_v2[NROWS*64];
__device__ float g_wc[NROWS*64];   // wl_e * c[b,v,e]
__device__ float g_wq[NROWS*64];   // wl_e * qh[b,q,e]
__device__ float g_m [NROWS*64];
__device__ float g_Aw[NROWS];      // sum_e wc
__device__ float g_Bw[NROWS];      // sum_e wq

static __device__ __forceinline__ ull f2add(ull a, ull b){ ull r; asm("add.rn.f32x2 %0,%1,%2;":"=l"(r):"l"(a),"l"(b)); return r; }
static __device__ __forceinline__ ull f2fma(ull a, ull b, ull c){ ull r; asm("fma.rn.f32x2 %0,%1,%2,%3;":"=l"(r):"l"(a),"l"(b),"l"(c)); return r; }
static __device__ __forceinline__ ull fsplat(float x){ ull r; asm("mov.b64 %0,{%1,%1};":"=l"(r):"f"(x)); return r; }
static __device__ __forceinline__ float2 funpack(ull v){ float2 f; asm("mov.b64 {%0,%1},%2;":"=f"(f.x),"=f"(f.y):"l"(v)); return f; }
static __device__ __forceinline__ float lrelu(float x){ return fmaxf(x,0.f) + 0.01f*fminf(x,0.f); }

static __device__ __forceinline__ unsigned sa(const void* p){
    unsigned a; asm("{ .reg .u64 t0; cvta.to.shared.u64 t0, %1; cvt.u32.u64 %0, t0; }":"=r"(a):"l"(p)); return a; }
#define CPA8(d,s) asm volatile("cp.async.ca.shared.global [%0], [%1], 8;"::"r"(sa(d)),"l"(s))
#define CPAC()  asm volatile("cp.async.commit_group;")
#define CPAW0() asm volatile("cp.async.wait_group 0;")
#define CPAW1() asm volatile("cp.async.wait_group 1;")

// ---------------------------------------------------------------------------
// K1: fused MLP (+embed on iter0). 16 rows/block, 128 blocks x 256 threads.
// ---------------------------------------------------------------------------
#define MLPS (5*4224 + 3*1024 + 64)

__global__ void __launch_bounds__(256) k_mlp(
    const float* __restrict__ vert, const float* __restrict__ We, const float* __restrict__ be,
    const float* __restrict__ Wm, const float* __restrict__ bm,
    const float* __restrict__ Wq, const float* __restrict__ bq,
    const float* __restrict__ Wch,const float* __restrict__ bch,
    const float* __restrict__ wl)
{
    extern __shared__ float sm[];
    float* Wm_s = sm;                 // 64*66
    float* Wq_s = sm + 4224;          // 3*64*66
    float* Wch_s= sm + 4*4224;        // 64*66
    float* vS   = sm + 5*4224;        // 16*64
    float* v2S  = vS + 1024;          // 16*64
    float* qS   = v2S + 1024;         // 16*64
    float* wl_s = qS + 1024;          // 64

    const int t = threadIdx.x;
    const int row0 = blockIdx.x*16;

    #pragma unroll
    for (int j=0;j<8;j++){ int p=t+j*256, k=p>>5, c=(p&31)*2; CPA8(&Wm_s[k*66+c], &Wm[k*64+c]); }
    if (t<32) CPA8(&wl_s[2*t], &wl[2*t]);
    if (!vert){
        #pragma unroll
        for (int j=0;j<2;j++){ int p=t+j*256, r=p>>5, c=(p&31)*2; CPA8(&vS[r*64+c], &g_v[(row0+r)*64+c]); }
    }
    CPAC();
    #pragma unroll
    for (int g=0; g<3; g++)
        #pragma unroll
        for (int j=0;j<8;j++){ int p=t+j*256, k=p>>5, c=(p&31)*2; CPA8(&Wq_s[g*4224+k*66+c], &Wq[k*192+g*64+c]); }
    #pragma unroll
    for (int j=0;j<8;j++){ int p=t+j*256, k=p>>5, c=(p&31)*2; CPA8(&Wch_s[k*66+c], &Wch[k*64+c]); }
    CPAC();

    if (vert){
        #pragma unroll
        for (int j=0;j<2;j++){
            int p=t+j*256, r=p>>5, c=(p&31)*2; int row=row0+r;
            float x=__ldg(&vert[row*3]), y=__ldg(&vert[row*3+1]), z=__ldg(&vert[row*3+2]);
            vS[r*64+c]   = __ldg(&be[c])   + x*__ldg(&We[c])   + y*__ldg(&We[64+c])   + z*__ldg(&We[128+c]);
            vS[r*64+c+1] = __ldg(&be[c+1]) + x*__ldg(&We[c+1]) + y*__ldg(&We[64+c+1]) + z*__ldg(&We[128+c+1]);
        }
    }
    CPAW1(); __syncthreads();

    const int r0 = (t>>5)*2, r1 = r0+1, c0 = (t&31)*2;
    const int rowA = row0 + r0, rowB = row0 + r1;

    // ---- phase 1 ----
    {
        float a00=0,a01=0,a10=0,a11=0;
        #pragma unroll
        for (int k=0;k<64;k++){
            float2 w = *(const float2*)&Wm_s[k*66+c0];
            float vA = vS[r0*64+k], vB = vS[r1*64+k];
            a00 += vA*w.x; a01 += vA*w.y; a10 += vB*w.x; a11 += vB*w.y;
        }
        float b0=__ldg(&bm[c0]), b1=__ldg(&bm[c0+1]);
        float xA0=vS[r0*64+c0], xA1=vS[r0*64+c0+1], xB0=vS[r1*64+c0], xB1=vS[r1*64+c0+1];
        float v2A0 = xA0 + lrelu(a00+b0+xA0);
        float v2A1 = xA1 + lrelu(a01+b1+xA1);
        float v2B0 = xB0 + lrelu(a10+b0+xB0);
        float v2B1 = xB1 + lrelu(a11+b1+xB1);
        v2S[r0*64+c0]=v2A0; v2S[r0*64+c0+1]=v2A1;
        v2S[r1*64+c0]=v2B0; v2S[r1*64+c0+1]=v2B1;
        *(float2*)&g_v2[rowA*64+c0] = make_float2(v2A0,v2A1);
        *(float2*)&g_v2[rowB*64+c0] = make_float2(v2B0,v2B1);
    }
    CPAW0(); __syncthreads();

    // ---- phase 2 ----
    {
        float aq0A=0,aq1A=0,aq0B=0,aq1B=0, ac0A=0,ac1A=0,ac0B=0,ac1B=0, am0A=0,am1A=0,am0B=0,am1B=0;
        #pragma unroll 8
        for (int k=0;k<64;k++){
            float vA = v2S[r0*64+k], vB = v2S[r1*64+k];
            float2 wq_ = *(const float2*)&Wq_s[       k*66+c0];
            float2 wc_ = *(const float2*)&Wq_s[4224 + k*66+c0];
            float2 wm_ = *(const float2*)&Wq_s[8448 + k*66+c0];
            aq0A+=vA*wq_.x; aq1A+=vA*wq_.y; aq0B+=vB*wq_.x; aq1B+=vB*wq_.y;
            ac0A+=vA*wc_.x; ac1A+=vA*wc_.y; ac0B+=vB*wc_.x; ac1B+=vB*wc_.y;
            am0A+=vA*wm_.x; am1A+=vA*wm_.y; am0B+=vB*wm_.x; am1B+=vB*wm_.y;
        }
        float bq0=__ldg(&bq[c0]), bq1=__ldg(&bq[c0+1]);
        qS[r0*64+c0]=aq0A+bq0; qS[r0*64+c0+1]=aq1A+bq1;
        qS[r1*64+c0]=aq0B+bq0; qS[r1*64+c0+1]=aq1B+bq1;

        float bc0=__ldg(&bq[64+c0]), bc1=__ldg(&bq[64+c0+1]);
        float wl0=wl_s[c0], wl1=wl_s[c0+1];
        float wcA0=wl0*(ac0A+bc0), wcA1=wl1*(ac1A+bc1);
        float wcB0=wl0*(ac0B+bc0), wcB1=wl1*(ac1B+bc1);
        *(float2*)&g_wc[rowA*64+c0] = make_float2(wcA0,wcA1);
        *(float2*)&g_wc[rowB*64+c0] = make_float2(wcB0,wcB1);
        float sA=wcA0+wcA1, sB=wcB0+wcB1;
        for (int off=16; off; off>>=1){ sA += __shfl_xor_sync(~0u,sA,off); sB += __shfl_xor_sync(~0u,sB,off); }
        if ((t&31)==0){ g_Aw[rowA]=sA; g_Aw[rowB]=sB; }

        float bmm0=__ldg(&bq[128+c0]), bmm1=__ldg(&bq[128+c0+1]);
        *(float2*)&g_m[rowA*64+c0] = make_float2(am0A+bmm0, am1A+bmm1);
        *(float2*)&g_m[rowB*64+c0] = make_float2(am0B+bmm0, am1B+bmm1);
    }
    __syncwarp();

    // ---- phase 3 ----
    {
        float a00=0,a01=0,a10=0,a11=0;
        #pragma unroll
        for (int k=0;k<64;k++){
            float2 w = *(const float2*)&Wch_s[k*66+c0];
            float qA = qS[r0*64+k], qB = qS[r1*64+k];
            a00 += qA*w.x; a01 += qA*w.y; a10 += qB*w.x; a11 += qB*w.y;
        }
        float b0=__ldg(&bch[c0]), b1=__ldg(&bch[c0+1]);
        float wl0=wl_s[c0], wl1=wl_s[c0+1];
        float wqA0=wl0*(a00+b0), wqA1=wl1*(a01+b1);
        float wqB0=wl0*(a10+b0), wqB1=wl1*(a11+b1);
        *(float2*)&g_wq[rowA*64+c0] = make_float2(wqA0,wqA1);
        *(float2*)&g_wq[rowB*64+c0] = make_float2(wqB0,wqB1);
        float sA=wqA0+wqA1, sB=wqB0+wqB1;
        for (int off=16; off; off>>=1){ sA += __shfl_xor_sync(~0u,sA,off); sB += __shfl_xor_sync(~0u,sB,off); }
        if ((t&31)==0){ g_Bw[rowA]=sA; g_Bw[rowB]=sB; }
    }
}

// ---------------------------------------------------------------------------
// K2: attention, double-buffered 128-v chunks. 8 q/block, grid (64,B), 256 thr.
// Pipeline: G0{init+wc0->A} G1{wc1->B} | c0:compute A, issue wc2->A | c1: B,
// wc3->B | c2: A, m0->A | c3: B, m1->B | softmax | m-chunks 0..3 same pattern
// issuing m2,m3,Wr | combine | final GEMM.
// ---------------------------------------------------------------------------
#define ATTNS (2*8448 + 4096 + 512 + 512 + 528 + 512 + 64 + 8 + 528 + 2048)

__global__ void __launch_bounds__(256) k_attn(float* __restrict__ dout,
    const float* __restrict__ wl, const float* __restrict__ bl,
    const float* __restrict__ Wr, const float* __restrict__ br,
    const float* __restrict__ temp, const float* __restrict__ maskp)
{
    extern __shared__ float sm[];
    float* bufA  = sm;                    // 128*66
    float* bufB  = sm + 8448;             // 128*66
    float* L     = sm + 2*8448;           // 8*512
    float* Aws   = L + 4096;              // 512
    float* lms   = Aws + 512;             // 512
    float* wqs   = lms + 512;             // 8*66
    float* v2s   = wqs + 528;             // 8*64
    float* s2s   = v2s + 512;             // 64
    float* Bws   = s2s + 64;              // 8
    float* heads = Bws + 8;               // 8*66
    ull*   hpart = (ull*)(heads + 528);   // 1024 ull

    const int t = threadIdx.x;
    const int b = blockIdx.y;
    const int rbase = b*NVERT + blockIdx.x*8;
    const float* wcBase = &g_wc[b*NVERT*64];
    const float* mBase  = &g_m [b*NVERT*64];

    // ---- G0: init staging + wc chunk0 -> A ----
    { int r=t>>5, c=(t&31)*2;
      CPA8(&wqs[r*66+c], &g_wq[(rbase+r)*64+c]);
      CPA8(&v2s[r*64+c], &g_v2[(rbase+r)*64+c]); }
    CPA8(&Aws[2*t], &g_Aw[b*NVERT+2*t]);
    CPA8(&lms[2*t], &maskp[b*NVERT+2*t]);
    if (t<4) CPA8(&Bws[2*t], &g_Bw[rbase+2*t]);
    #pragma unroll
    for (int j=0;j<16;j++){ int p=t+j*256, r=p>>5, c=(p&31)*2;
        CPA8(&bufA[r*66+c], &wcBase[r*64+c]); }
    CPAC();
    // ---- G1: wc chunk1 -> B ----
    #pragma unroll
    for (int j=0;j<16;j++){ int p=t+j*256, r=p>>5, c=(p&31)*2;
        CPA8(&bufB[r*66+c], &wcBase[(128+r)*64+c]); }
    CPAC();

    if (t<64) s2s[t] = copysignf(0.495f, __ldg(&wl[t]));
    const float bl0  = __ldg(&bl[0]);
    const float invt = 1.0f/__ldg(&temp[0]);

    // ---- pass A: 4 chunks of 128 v ----
    const int qt = t>>6;            // 0..3 -> q pair
    const int q0 = qt*2;
    const int vl = t&63;            // v rows vl, vl+64 within chunk

    #pragma unroll
    for (int ck=0; ck<4; ck++){
        CPAW1(); __syncthreads();
        const float* buf = (ck&1)? bufB : bufA;
        const ull* pcA = (const ull*)&buf[ vl     *66];
        const ull* pcB = (const ull*)&buf[(vl+64) *66];
        const ull* pq0 = (const ull*)&wqs[ q0   *66];
        const ull* pq1 = (const ull*)&wqs[(q0+1)*66];
        const ull* s2p = (const ull*)s2s;

        ull a00=0,a01=0,a10=0,a11=0;
        #pragma unroll 8
        for (int ep=0; ep<32; ep++){
            ull cA = pcA[ep], cB = pcB[ep], s = s2p[ep];
            ull w0 = pq0[ep], w1 = pq1[ep];
            a00 = f2fma(s, f2add(cA,w0)&ABS2, a00);
            a01 = f2fma(s, f2add(cB,w0)&ABS2, a01);
            a10 = f2fma(s, f2add(cA,w1)&ABS2, a10);
            a11 = f2fma(s, f2add(cB,w1)&ABS2, a11);
        }
        {
            int vgA = ck*128 + vl, vgB = vgA + 64;
            float bA = 0.505f*Aws[vgA] + bl0, bB = 0.505f*Aws[vgB] + bl0;
            float lmA = lms[vgA], lmB = lms[vgB];
            float2 f00=funpack(a00), f01=funpack(a01), f10=funpack(a10), f11=funpack(a11);
            float B0 = 0.505f*Bws[q0], B1 = 0.505f*Bws[q0+1];
            L[ q0   *512+vgA] = (bA+B0+f00.x+f00.y)*invt*lmA - 99999.f*(1.f-lmA);
            L[ q0   *512+vgB] = (bB+B0+f01.x+f01.y)*invt*lmB - 99999.f*(1.f-lmB);
            L[(q0+1)*512+vgA] = (bA+B1+f10.x+f10.y)*invt*lmA - 99999.f*(1.f-lmA);
            L[(q0+1)*512+vgB] = (bB+B1+f11.x+f11.y)*invt*lmB - 99999.f*(1.f-lmB);
        }
        __syncthreads();
        // issue next stage: wc2->A, wc3->B, m0->A, m1->B
        const float* src = (ck<2)? &wcBase[(ck+2)*128*64] : &mBase[(ck-2)*128*64];
        float* dst = (ck&1)? bufB : bufA;
        #pragma unroll
        for (int j=0;j<16;j++){ int p=t+j*256, r=p>>5, c=(p&31)*2;
            CPA8(&dst[r*66+c], &src[r*64+c]); }
        CPAC();
    }

    // ---- pass B: softmax (warp w handles q-row w) ----
    {
        const int lane = t&31, w = t>>5;
        float lv[16];
        #pragma unroll
        for (int j=0;j<16;j++) lv[j] = L[w*512 + lane + 32*j];
        float mx = lv[0];
        #pragma unroll
        for (int j=1;j<16;j++) mx = fmaxf(mx, lv[j]);
        for (int off=16; off; off>>=1) mx = fmaxf(mx, __shfl_xor_sync(~0u, mx, off));
        float ev[16], ssum=0.f;
        #pragma unroll
        for (int j=0;j<16;j++){ ev[j] = __expf(lv[j]-mx); ssum += ev[j]; }
        for (int off=16; off; off>>=1) ssum += __shfl_xor_sync(~0u, ssum, off);
        float inv = 1.0f/ssum;
        #pragma unroll
        for (int j=0;j<16;j++) L[w*512 + lane + 32*j] = ev[j]*inv*lms[lane+32*j];
    }
    __syncthreads();

    // ---- pass C: heads = probs @ m, 4 chunks of 128 v ----
    const int ep  = t&31;
    const int sr  = (t>>5)&3;     // 32-v subrange within chunk
    const int qg  = t>>7;         // 4 q's
    ull acc[4] = {0,0,0,0};

    #pragma unroll
    for (int ck=0; ck<4; ck++){
        CPAW1(); __syncthreads();
        const float* buf = (ck&1)? bufB : bufA;
        const float* L0 = &L[(qg*4+0)*512 + ck*128 + sr*32];
        const float* L1 = &L[(qg*4+1)*512 + ck*128 + sr*32];
        const float* L2 = &L[(qg*4+2)*512 + ck*128 + sr*32];
        const float* L3 = &L[(qg*4+3)*512 + ck*128 + sr*32];
        #pragma unroll 4
        for (int vv=0; vv<32; vv+=4){
            ull m0 = *(const ull*)&buf[(sr*32+vv+0)*66 + 2*ep];
            ull m1 = *(const ull*)&buf[(sr*32+vv+1)*66 + 2*ep];
            ull m2 = *(const ull*)&buf[(sr*32+vv+2)*66 + 2*ep];
            ull m3 = *(const ull*)&buf[(sr*32+vv+3)*66 + 2*ep];
            float4 p0 = *(const float4*)&L0[vv];
            float4 p1 = *(const float4*)&L1[vv];
            float4 p2 = *(const float4*)&L2[vv];
            float4 p3 = *(const float4*)&L3[vv];
            acc[0]=f2fma(fsplat(p0.x),m0,acc[0]); acc[0]=f2fma(fsplat(p0.y),m1,acc[0]);
            acc[0]=f2fma(fsplat(p0.z),m2,acc[0]); acc[0]=f2fma(fsplat(p0.w),m3,acc[0]);
            acc[1]=f2fma(fsplat(p1.x),m0,acc[1]); acc[1]=f2fma(fsplat(p1.y),m1,acc[1]);
            acc[1]=f2fma(fsplat(p1.z),m2,acc[1]); acc[1]=f2fma(fsplat(p1.w),m3,acc[1]);
            acc[2]=f2fma(fsplat(p2.x),m0,acc[2]); acc[2]=f2fma(fsplat(p2.y),m1,acc[2]);
            acc[2]=f2fma(fsplat(p2.z),m2,acc[2]); acc[2]=f2fma(fsplat(p2.w),m3,acc[2]);
            acc[3]=f2fma(fsplat(p3.x),m0,acc[3]); acc[3]=f2fma(fsplat(p3.y),m1,acc[3]);
            acc[3]=f2fma(fsplat(p3.z),m2,acc[3]); acc[3]=f2fma(fsplat(p3.w),m3,acc[3]);
        }
        __syncthreads();
        if (ck<2){          // m2->A, m3->B
            float* dst = (ck&1)? bufB : bufA;
            const float* src = &mBase[(ck+2)*128*64];
            #pragma unroll
            for (int j=0;j<16;j++){ int p=t+j*256, r=p>>5, c=(p&31)*2;
                CPA8(&dst[r*66+c], &src[r*64+c]); }
            CPAC();
        } else if (ck==2){  // Wr->A
            #pragma unroll
            for (int j=0;j<8;j++){ int p=t+j*256, k=p>>5, c=(p&31)*2;
                CPA8(&bufA[k*66+c], &Wr[k*64+c]); }
            CPAC();
        }
    }
    #pragma unroll
    for (int i=0;i<4;i++) hpart[((sr*2+qg)*32+ep)*4+i] = acc[i];
    __syncthreads();

    // combine partials -> heads (lrelu)
    {
        const int tq = t>>5, tep = t&31;
        const int hqg = tq>>2, hi = tq&3;
        ull s = f2add(f2add(hpart[((0*2+hqg)*32+tep)*4+hi], hpart[((1*2+hqg)*32+tep)*4+hi]),
                      f2add(hpart[((2*2+hqg)*32+tep)*4+hi], hpart[((3*2+hqg)*32+tep)*4+hi]));
        float2 hv = funpack(s);
        heads[tq*66+2*tep]   = lrelu(hv.x);
        heads[tq*66+2*tep+1] = lrelu(hv.y);
    }
    CPAW0(); __syncthreads();

    // ---- final: out = lrelu(heads)@Wr + br + v2  (Wr in bufA) ----
    {
        const int q = t>>5, c0 = (t&31)*2;
        ull oacc = 0;
        #pragma unroll 8
        for (int e=0; e<64; e++)
            oacc = f2fma(fsplat(heads[q*66+e]), *(const ull*)&bufA[e*66+c0], oacc);
        float2 o = funpack(oacc);
        int row = rbase + q;
        float r0v = o.x + __ldg(&br[c0])   + v2s[q*64+c0];
        float r1v = o.y + __ldg(&br[c0+1]) + v2s[q*64+c0+1];
        *(float2*)&g_v[row*64+c0] = make_float2(r0v, r1v);
        if (dout) *(float2*)&dout[row*64+c0] = make_float2(r0v, r1v);
    }
}

// ---------------------------------------------------------------------------
extern "C" void kernel_launch(void* const* d_in, const int* in_sizes, int n_in,
                              void* d_out, int out_size)
{
    const float* vertices = (const float*)d_in[0];
    const float* mask     = (const float*)d_in[1];
    const float* W_embed  = (const float*)d_in[2];
    const float* b_embed  = (const float*)d_in[3];
    const float* W_mlp    = (const float*)d_in[4];
    const float* b_mlp    = (const float*)d_in[5];
    const float* W_qcm    = (const float*)d_in[6];
    const float* b_qcm    = (const float*)d_in[7];
    const float* W_ch     = (const float*)d_in[8];
    const float* b_ch     = (const float*)d_in[9];
    const float* W_logit  = (const float*)d_in[10];
    const float* b_logit  = (const float*)d_in[11];
    const float* W_red    = (const float*)d_in[12];
    const float* b_red    = (const float*)d_in[13];
    const float* temp     = (const float*)d_in[14];
    float* out = (float*)d_out;

    const int mlp_smem  = MLPS*4;
    const int attn_smem = ATTNS*4;
    cudaFuncSetAttribute(k_mlp,  cudaFuncAttributeMaxDynamicSharedMemorySize, mlp_smem);
    cudaFuncSetAttribute(k_attn, cudaFuncAttributeMaxDynamicSharedMemorySize, attn_smem);

    for (int i=0; i<3; i++){
        k_mlp<<<128,256,mlp_smem>>>(i==0 ? vertices : (const float*)nullptr, W_embed, b_embed,
                                    W_mlp + i*4096, b_mlp + i*64,
                                    W_qcm + i*12288, b_qcm + i*192,
                                    W_ch  + i*4096, b_ch  + i*64,
                                    W_logit + i*64);
        k_attn<<<dim3(64,NBATCH),256,attn_smem>>>(i==2 ? out : (float*)nullptr,
                                                  W_logit + i*64, b_logit + i,
                                                  W_red + i*4096, b_red + i*64,
                                                  temp + i, mask);
    }
}

// round 7
// speedup vs baseline: 1.0421x; 1.0421x over previous
#include <cuda_runtime.h>

typedef unsigned long long ull;
#define NBATCH 4
#define NVERT 512
#define NROWS (NBATCH*NVERT)
#define ABS2 0x7fffffff7fffffffULL

// scratch (allocation-free rule: device globals). 256B-aligned for cp.async.16.
__device__ __align__(256) float g_v [NROWS*64];
__device__ __align__(256) float g_v2[NROWS*64];
__device__ __align__(256) float g_wc[NROWS*64];   // wl_e * c[b,v,e]
__device__ __align__(256) float g_wq[NROWS*64];   // wl_e * qh[b,q,e]
__device__ __align__(256) float g_m [NROWS*64];
__device__ __align__(256) float g_Aw[NROWS];      // sum_e wc
__device__ __align__(256) float g_Bw[NROWS];      // sum_e wq

static __device__ __forceinline__ ull f2add(ull a, ull b){ ull r; asm("add.rn.f32x2 %0,%1,%2;":"=l"(r):"l"(a),"l"(b)); return r; }
static __device__ __forceinline__ ull f2fma(ull a, ull b, ull c){ ull r; asm("fma.rn.f32x2 %0,%1,%2,%3;":"=l"(r):"l"(a),"l"(b),"l"(c)); return r; }
static __device__ __forceinline__ ull fsplat(float x){ ull r; asm("mov.b64 %0,{%1,%1};":"=l"(r):"f"(x)); return r; }
static __device__ __forceinline__ float2 funpack(ull v){ float2 f; asm("mov.b64 {%0,%1},%2;":"=f"(f.x),"=f"(f.y):"l"(v)); return f; }
static __device__ __forceinline__ float lrelu(float x){ return fmaxf(x,0.f) + 0.01f*fminf(x,0.f); }

static __device__ __forceinline__ unsigned sa(const void* p){
    unsigned a; asm("{ .reg .u64 t0; cvta.to.shared.u64 t0, %1; cvt.u32.u64 %0, t0; }":"=r"(a):"l"(p)); return a; }
#define CPA8(d,s)  asm volatile("cp.async.ca.shared.global [%0], [%1], 8;"::"r"(sa(d)),"l"(s))
#define CPA16(d,s) asm volatile("cp.async.cg.shared.global [%0], [%1], 16;"::"r"(sa(d)),"l"(s))
#define CPAC()  asm volatile("cp.async.commit_group;")
#define CPAW0() asm volatile("cp.async.wait_group 0;")
#define CPAW1() asm volatile("cp.async.wait_group 1;")

// ---------------------------------------------------------------------------
// K1: fused MLP (+embed on iter0). 16 rows/block, 128 blocks x 256 threads.
// (unchanged from round 4 — measured 3.3us, correct; CPA8 = 2 floats)
// ---------------------------------------------------------------------------
#define MLPS (5*4224 + 3*1024 + 64)

__global__ void __launch_bounds__(256) k_mlp(
    const float* __restrict__ vert, const float* __restrict__ We, const float* __restrict__ be,
    const float* __restrict__ Wm, const float* __restrict__ bm,
    const float* __restrict__ Wq, const float* __restrict__ bq,
    const float* __restrict__ Wch,const float* __restrict__ bch,
    const float* __restrict__ wl)
{
    extern __shared__ float sm[];
    float* Wm_s = sm;                 // 64*66
    float* Wq_s = sm + 4224;          // 3*64*66
    float* Wch_s= sm + 4*4224;        // 64*66
    float* vS   = sm + 5*4224;        // 16*64
    float* v2S  = vS + 1024;          // 16*64
    float* qS   = v2S + 1024;         // 16*64
    float* wl_s = qS + 1024;          // 64

    const int t = threadIdx.x;
    const int row0 = blockIdx.x*16;

    #pragma unroll
    for (int j=0;j<8;j++){ int p=t+j*256, k=p>>5, c=(p&31)*2; CPA8(&Wm_s[k*66+c], &Wm[k*64+c]); }
    if (t<32) CPA8(&wl_s[2*t], &wl[2*t]);
    if (!vert){
        #pragma unroll
        for (int j=0;j<2;j++){ int p=t+j*256, r=p>>5, c=(p&31)*2; CPA8(&vS[r*64+c], &g_v[(row0+r)*64+c]); }
    }
    CPAC();
    #pragma unroll
    for (int g=0; g<3; g++)
        #pragma unroll
        for (int j=0;j<8;j++){ int p=t+j*256, k=p>>5, c=(p&31)*2; CPA8(&Wq_s[g*4224+k*66+c], &Wq[k*192+g*64+c]); }
    #pragma unroll
    for (int j=0;j<8;j++){ int p=t+j*256, k=p>>5, c=(p&31)*2; CPA8(&Wch_s[k*66+c], &Wch[k*64+c]); }
    CPAC();

    if (vert){
        #pragma unroll
        for (int j=0;j<2;j++){
            int p=t+j*256, r=p>>5, c=(p&31)*2; int row=row0+r;
            float x=__ldg(&vert[row*3]), y=__ldg(&vert[row*3+1]), z=__ldg(&vert[row*3+2]);
            vS[r*64+c]   = __ldg(&be[c])   + x*__ldg(&We[c])   + y*__ldg(&We[64+c])   + z*__ldg(&We[128+c]);
            vS[r*64+c+1] = __ldg(&be[c+1]) + x*__ldg(&We[c+1]) + y*__ldg(&We[64+c+1]) + z*__ldg(&We[128+c+1]);
        }
    }
    CPAW1(); __syncthreads();

    const int r0 = (t>>5)*2, r1 = r0+1, c0 = (t&31)*2;
    const int rowA = row0 + r0, rowB = row0 + r1;

    // phase 1
    {
        float a00=0,a01=0,a10=0,a11=0;
        #pragma unroll
        for (int k=0;k<64;k++){
            float2 w = *(const float2*)&Wm_s[k*66+c0];
            float vA = vS[r0*64+k], vB = vS[r1*64+k];
            a00 += vA*w.x; a01 += vA*w.y; a10 += vB*w.x; a11 += vB*w.y;
        }
        float b0=__ldg(&bm[c0]), b1=__ldg(&bm[c0+1]);
        float xA0=vS[r0*64+c0], xA1=vS[r0*64+c0+1], xB0=vS[r1*64+c0], xB1=vS[r1*64+c0+1];
        float v2A0 = xA0 + lrelu(a00+b0+xA0);
        float v2A1 = xA1 + lrelu(a01+b1+xA1);
        float v2B0 = xB0 + lrelu(a10+b0+xB0);
        float v2B1 = xB1 + lrelu(a11+b1+xB1);
        v2S[r0*64+c0]=v2A0; v2S[r0*64+c0+1]=v2A1;
        v2S[r1*64+c0]=v2B0; v2S[r1*64+c0+1]=v2B1;
        *(float2*)&g_v2[rowA*64+c0] = make_float2(v2A0,v2A1);
        *(float2*)&g_v2[rowB*64+c0] = make_float2(v2B0,v2B1);
    }
    CPAW0(); __syncthreads();

    // phase 2
    {
        float aq0A=0,aq1A=0,aq0B=0,aq1B=0, ac0A=0,ac1A=0,ac0B=0,ac1B=0, am0A=0,am1A=0,am0B=0,am1B=0;
        #pragma unroll 8
        for (int k=0;k<64;k++){
            float vA = v2S[r0*64+k], vB = v2S[r1*64+k];
            float2 wq_ = *(const float2*)&Wq_s[       k*66+c0];
            float2 wc_ = *(const float2*)&Wq_s[4224 + k*66+c0];
            float2 wm_ = *(const float2*)&Wq_s[8448 + k*66+c0];
            aq0A+=vA*wq_.x; aq1A+=vA*wq_.y; aq0B+=vB*wq_.x; aq1B+=vB*wq_.y;
            ac0A+=vA*wc_.x; ac1A+=vA*wc_.y; ac0B+=vB*wc_.x; ac1B+=vB*wc_.y;
            am0A+=vA*wm_.x; am1A+=vA*wm_.y; am0B+=vB*wm_.x; am1B+=vB*wm_.y;
        }
        float bq0=__ldg(&bq[c0]), bq1=__ldg(&bq[c0+1]);
        qS[r0*64+c0]=aq0A+bq0; qS[r0*64+c0+1]=aq1A+bq1;
        qS[r1*64+c0]=aq0B+bq0; qS[r1*64+c0+1]=aq1B+bq1;

        float bc0=__ldg(&bq[64+c0]), bc1=__ldg(&bq[64+c0+1]);
        float wl0=wl_s[c0], wl1=wl_s[c0+1];
        float wcA0=wl0*(ac0A+bc0), wcA1=wl1*(ac1A+bc1);
        float wcB0=wl0*(ac0B+bc0), wcB1=wl1*(ac1B+bc1);
        *(float2*)&g_wc[rowA*64+c0] = make_float2(wcA0,wcA1);
        *(float2*)&g_wc[rowB*64+c0] = make_float2(wcB0,wcB1);
        float sA=wcA0+wcA1, sB=wcB0+wcB1;
        for (int off=16; off; off>>=1){ sA += __shfl_xor_sync(~0u,sA,off); sB += __shfl_xor_sync(~0u,sB,off); }
        if ((t&31)==0){ g_Aw[rowA]=sA; g_Aw[rowB]=sB; }

        float bmm0=__ldg(&bq[128+c0]), bmm1=__ldg(&bq[128+c0+1]);
        *(float2*)&g_m[rowA*64+c0] = make_float2(am0A+bmm0, am1A+bmm1);
        *(float2*)&g_m[rowB*64+c0] = make_float2(am0B+bmm0, am1B+bmm1);
    }
    __syncwarp();

    // phase 3
    {
        float a00=0,a01=0,a10=0,a11=0;
        #pragma unroll
        for (int k=0;k<64;k++){
            float2 w = *(const float2*)&Wch_s[k*66+c0];
            float qA = qS[r0*64+k], qB = qS[r1*64+k];
            a00 += qA*w.x; a01 += qA*w.y; a10 += qB*w.x; a11 += qB*w.y;
        }
        float b0=__ldg(&bch[c0]), b1=__ldg(&bch[c0+1]);
        float wl0=wl_s[c0], wl1=wl_s[c0+1];
        float wqA0=wl0*(a00+b0), wqA1=wl1*(a01+b1);
        float wqB0=wl0*(a10+b0), wqB1=wl1*(a11+b1);
        *(float2*)&g_wq[rowA*64+c0] = make_float2(wqA0,wqA1);
        *(float2*)&g_wq[rowB*64+c0] = make_float2(wqB0,wqB1);
        float sA=wqA0+wqA1, sB=wqB0+wqB1;
        for (int off=16; off; off>>=1){ sA += __shfl_xor_sync(~0u,sA,off); sB += __shfl_xor_sync(~0u,sB,off); }
        if ((t&31)==0){ g_Bw[rowA]=sA; g_Bw[rowB]=sB; }
    }
}

// ---------------------------------------------------------------------------
// K2: attention. 8 q/block, grid (64,B), 256 thr. Single 256-row buffer
// (stride 68), LDS.128 compute, cp.async.16 staging (16 BYTES = 4 floats!).
// Smem layout (floats):
//   buf   [0,17408)     : wc/m chunks (256x68); hpart aliases this at the end
//   L     [17408,21504) : 8x512 logits->probs
//   Wr_s  [21504,25856) : 64x68
//   wqs   [25856,26400) : 8x68
//   v2s   [26400,26912) : 8x64
//   s2s   [26912,26976) : 64
//   Aws   [26976,27488) : 512 ; Bws [27488,27496) ; heads aliases 26976.. after pass A
//   lms   [27520,28032) : 512
#define ATTNS 28032

__global__ void __launch_bounds__(256) k_attn(float* __restrict__ dout,
    const float* __restrict__ wl, const float* __restrict__ bl,
    const float* __restrict__ Wr, const float* __restrict__ br,
    const float* __restrict__ temp, const float* __restrict__ maskp)
{
    extern __shared__ float sm[];
    float* buf   = sm;
    float* L     = sm + 17408;
    float* Wr_s  = sm + 21504;
    float* wqs   = sm + 25856;
    float* v2s   = sm + 26400;
    float* s2s   = sm + 26912;
    float* Aws   = sm + 26976;
    float* Bws   = Aws + 512;
    float* heads = sm + 26976;           // alias of Aws/Bws (dead after pass A)
    float* lms   = sm + 27520;
    ull*   hpart = (ull*)sm;             // alias of buf (dead after pass C)

    const int t = threadIdx.x;
    const int b = blockIdx.y;
    const int rbase = b*NVERT + blockIdx.x*8;
    const float* wcBase = &g_wc[b*NVERT*64];
    const float* mBase  = &g_m [b*NVERT*64];

    // ---- prologue staging, all in one commit group. CPA16 = 4 floats. ----
    if (t < 128){
        int r = t>>4, c = (t&15)*4;                         // wqs: 8x64 = 128 xfers
        CPA16(&wqs[r*68+c], &g_wq[(rbase+r)*64+c]);
        CPA16(&Aws[t*4], &g_Aw[b*NVERT + t*4]);             // Aws: 512 = 128 xfers
    } else {
        int u = t-128, r = u>>4, c = (u&15)*4;              // v2s: 8x64 = 128 xfers
        CPA16(&v2s[r*64+c], &g_v2[(rbase+r)*64+c]);
        CPA16(&lms[u*4], &maskp[b*NVERT + u*4]);            // lms: 512 = 128 xfers
    }
    if (t < 2) CPA16(&Bws[t*4], &g_Bw[rbase + t*4]);        // Bws: 8 = 2 xfers
    #pragma unroll
    for (int j=0;j<4;j++){ int p=t+j*256, r=p>>4, c=(p&15)*4;   // Wr: 64x64 = 1024
        CPA16(&Wr_s[r*68+c], &Wr[r*64+c]); }
    #pragma unroll
    for (int j=0;j<16;j++){ int p=t+j*256, r=p>>4, c=(p&15)*4;  // wc chunk0: 256x64
        CPA16(&buf[r*68+c], &wcBase[r*64+c]); }
    CPAC();
    if (t<64) s2s[t] = copysignf(0.495f, __ldg(&wl[t]));
    const float bl0  = __ldg(&bl[0]);
    const float invt = 1.0f/__ldg(&temp[0]);
    CPAW0(); __syncthreads();

    // ---- pass A: logits, 2 chunks of 256 v, tile 4q x 2v x 4e ----
    const int qt = t>>7, q0 = qt*4, vl = t&127;
    float Bq0 = 0.505f*Bws[q0],   Bq1 = 0.505f*Bws[q0+1];
    float Bq2 = 0.505f*Bws[q0+2], Bq3 = 0.505f*Bws[q0+3];

    #pragma unroll
    for (int ck=0; ck<2; ck++){
        if (ck==1){
            __syncthreads();   // all reads of buf done
            #pragma unroll
            for (int j=0;j<16;j++){ int p=t+j*256, r=p>>4, c=(p&15)*4;
                CPA16(&buf[r*68+c], &wcBase[(256+r)*64+c]); }
            CPAC(); CPAW0(); __syncthreads();
        }
        ull aA[4][2] = {{0,0},{0,0},{0,0},{0,0}};
        ull aB[4][2] = {{0,0},{0,0},{0,0},{0,0}};
        #pragma unroll 4
        for (int eb=0; eb<16; eb++){
            ulonglong2 cA = *(const ulonglong2*)&buf[ vl     *68 + eb*4];
            ulonglong2 cB = *(const ulonglong2*)&buf[(vl+128)*68 + eb*4];
            ulonglong2 s  = *(const ulonglong2*)&s2s[eb*4];
            #pragma unroll
            for (int i=0;i<4;i++){
                ulonglong2 w = *(const ulonglong2*)&wqs[(q0+i)*68 + eb*4];
                aA[i][0] = f2fma(s.x, f2add(cA.x,w.x)&ABS2, aA[i][0]);
                aA[i][1] = f2fma(s.y, f2add(cA.y,w.y)&ABS2, aA[i][1]);
                aB[i][0] = f2fma(s.x, f2add(cB.x,w.x)&ABS2, aB[i][0]);
                aB[i][1] = f2fma(s.y, f2add(cB.y,w.y)&ABS2, aB[i][1]);
            }
        }
        int vgA = ck*256 + vl, vgB = vgA + 128;
        float baseA = 0.505f*Aws[vgA] + bl0, baseB = 0.505f*Aws[vgB] + bl0;
        float lmA = lms[vgA], lmB = lms[vgB];
        float pA = invt*lmA, mA = -99999.f*(1.f-lmA);
        float pB = invt*lmB, mB = -99999.f*(1.f-lmB);
        float Bq[4] = {Bq0,Bq1,Bq2,Bq3};
        #pragma unroll
        for (int i=0;i<4;i++){
            float2 fA = funpack(f2add(aA[i][0],aA[i][1]));
            float2 fB = funpack(f2add(aB[i][0],aB[i][1]));
            L[(q0+i)*512 + vgA] = (baseA + Bq[i] + fA.x + fA.y)*pA + mA;
            L[(q0+i)*512 + vgB] = (baseB + Bq[i] + fB.x + fB.y)*pB + mB;
        }
    }
    __syncthreads();

    // prefetch m chunk0 under softmax
    #pragma unroll
    for (int j=0;j<16;j++){ int p=t+j*256, r=p>>4, c=(p&15)*4;
        CPA16(&buf[r*68+c], &mBase[r*64+c]); }
    CPAC();

    // ---- pass B: softmax (warp w handles q-row w) ----
    {
        const int lane = t&31, w = t>>5;
        float lv[16];
        #pragma unroll
        for (int j=0;j<16;j++) lv[j] = L[w*512 + lane + 32*j];
        float mx = lv[0];
        #pragma unroll
        for (int j=1;j<16;j++) mx = fmaxf(mx, lv[j]);
        for (int off=16; off; off>>=1) mx = fmaxf(mx, __shfl_xor_sync(~0u, mx, off));
        float ev[16], ssum=0.f;
        #pragma unroll
        for (int j=0;j<16;j++){ ev[j] = __expf(lv[j]-mx); ssum += ev[j]; }
        for (int off=16; off; off>>=1) ssum += __shfl_xor_sync(~0u, ssum, off);
        float inv = 1.0f/ssum;
        #pragma unroll
        for (int j=0;j<16;j++) L[w*512 + lane + 32*j] = ev[j]*inv*lms[lane+32*j];
    }
    CPAW0(); __syncthreads();

    // ---- pass C: heads = probs @ m, 2 chunks; tile 4q x 4v x 4e ----
    const int em = t&15;          // e block (4 e)
    const int sv = (t>>4)&7;      // 32-v subrange within chunk
    const int qg = t>>7;          // q group of 4
    const int qc0 = qg*4;
    ull acc[4][2] = {{0,0},{0,0},{0,0},{0,0}};

    #pragma unroll
    for (int ck=0; ck<2; ck++){
        if (ck==1){
            __syncthreads();
            #pragma unroll
            for (int j=0;j<16;j++){ int p=t+j*256, r=p>>4, c=(p&15)*4;
                CPA16(&buf[r*68+c], &mBase[(256+r)*64+c]); }
            CPAC(); CPAW0(); __syncthreads();
        }
        const int Lo = ck*256 + sv*32;
        #pragma unroll 2
        for (int vv=0; vv<32; vv+=4){
            int r = sv*32+vv;
            ulonglong2 m0 = *(const ulonglong2*)&buf[(r+0)*68 + em*4];
            ulonglong2 m1 = *(const ulonglong2*)&buf[(r+1)*68 + em*4];
            ulonglong2 m2 = *(const ulonglong2*)&buf[(r+2)*68 + em*4];
            ulonglong2 m3 = *(const ulonglong2*)&buf[(r+3)*68 + em*4];
            #pragma unroll
            for (int i=0;i<4;i++){
                float4 p = *(const float4*)&L[(qc0+i)*512 + Lo + vv];
                ull s0=fsplat(p.x), s1=fsplat(p.y), s2=fsplat(p.z), s3=fsplat(p.w);
                acc[i][0]=f2fma(s0,m0.x,acc[i][0]); acc[i][1]=f2fma(s0,m0.y,acc[i][1]);
                acc[i][0]=f2fma(s1,m1.x,acc[i][0]); acc[i][1]=f2fma(s1,m1.y,acc[i][1]);
                acc[i][0]=f2fma(s2,m2.x,acc[i][0]); acc[i][1]=f2fma(s2,m2.y,acc[i][1]);
                acc[i][0]=f2fma(s3,m3.x,acc[i][0]); acc[i][1]=f2fma(s3,m3.y,acc[i][1]);
            }
        }
    }
    __syncthreads();   // all buf reads done; hpart may now overwrite buf

    #pragma unroll
    for (int i=0;i<4;i++){
        hpart[(((sv*2+qg)*16+em)*4+i)*2+0] = acc[i][0];
        hpart[(((sv*2+qg)*16+em)*4+i)*2+1] = acc[i][1];
    }
    __syncthreads();

    // combine partials over sv -> heads (lrelu). heads aliases Aws (dead).
    {
        const int q = t>>5, uc = t&31;
        const int hem = uc>>1, hu = uc&1, hqg = q>>2, hi = q&3;
        ull s = 0;
        #pragma unroll
        for (int svi=0; svi<8; svi++)
            s = f2add(s, hpart[(((svi*2+hqg)*16+hem)*4+hi)*2+hu]);
        float2 hv = funpack(s);
        heads[q*68 + uc*2]   = lrelu(hv.x);
        heads[q*68 + uc*2+1] = lrelu(hv.y);
    }
    __syncthreads();

    // ---- final: out = lrelu(heads)@Wr + br + v2  (Wr in Wr_s from prologue) ----
    {
        const int q = t>>5, c0 = (t&31)*2;
        ull oacc = 0;
        #pragma unroll 8
        for (int e=0; e<64; e++)
            oacc = f2fma(fsplat(heads[q*68+e]), *(const ull*)&Wr_s[e*68+c0], oacc);
        float2 o = funpack(oacc);
        int row = rbase + q;
        float r0v = o.x + __ldg(&br[c0])   + v2s[q*64+c0];
        float r1v = o.y + __ldg(&br[c0+1]) + v2s[q*64+c0+1];
        *(float2*)&g_v[row*64+c0] = make_float2(r0v, r1v);
        if (dout) *(float2*)&dout[row*64+c0] = make_float2(r0v, r1v);
    }
}

// ---------------------------------------------------------------------------
extern "C" void kernel_launch(void* const* d_in, const int* in_sizes, int n_in,
                              void* d_out, int out_size)
{
    const float* vertices = (const float*)d_in[0];
    const float* mask     = (const float*)d_in[1];
    const float* W_embed  = (const float*)d_in[2];
    const float* b_embed  = (const float*)d_in[3];
    const float* W_mlp    = (const float*)d_in[4];
    const float* b_mlp    = (const float*)d_in[5];
    const float* W_qcm    = (const float*)d_in[6];
    const float* b_qcm    = (const float*)d_in[7];
    const float* W_ch     = (const float*)d_in[8];
    const float* b_ch     = (const float*)d_in[9];
    const float* W_logit  = (const float*)d_in[10];
    const float* b_logit  = (const float*)d_in[11];
    const float* W_red    = (const float*)d_in[12];
    const float* b_red    = (const float*)d_in[13];
    const float* temp     = (const float*)d_in[14];
    float* out = (float*)d_out;

    const int mlp_smem  = MLPS*4;
    const int attn_smem = ATTNS*4;
    cudaFuncSetAttribute(k_mlp,  cudaFuncAttributeMaxDynamicSharedMemorySize, mlp_smem);
    cudaFuncSetAttribute(k_attn, cudaFuncAttributeMaxDynamicSharedMemorySize, attn_smem);

    for (int i=0; i<3; i++){
        k_mlp<<<128,256,mlp_smem>>>(i==0 ? vertices : (const float*)nullptr, W_embed, b_embed,
                                    W_mlp + i*4096, b_mlp + i*64,
                                    W_qcm + i*12288, b_qcm + i*192,
                                    W_ch  + i*4096, b_ch  + i*64,
                                    W_logit + i*64);
        k_attn<<<dim3(64,NBATCH),256,attn_smem>>>(i==2 ? out : (float*)nullptr,
                                                  W_logit + i*64, b_logit + i,
                                                  W_red + i*4096, b_red + i*64,
                                                  temp + i, mask);
    }
}